// round 6
// baseline (speedup 1.0000x reference)
#include <cuda_runtime.h>

// Shapes fixed by the reference: n=16, c=3, h=w=512
#define HW      262144          // 512*512
#define NB      16
#define CC      3
#define NHW     (NB * HW)       // 4194304 spatial positions (n,1,h,w)
#define HW4     (HW / 4)        // float4 elements per channel plane = 65536 = 2^16
#define NVEC    (NHW / 4)       // float4 elements in seg = 1048576

#define NBLOCKS  1024
#define NTHREADS 256
#define ITERS    (NVEC / (NBLOCKS * NTHREADS))   // = 4, exact tiling

// Per-block partials (device globals; no allocation allowed).
// Every slot is overwritten on every call -> no init pass, fully deterministic.
__device__ float        g_part_ts[NBLOCKS];
__device__ float        g_part_ps[NBLOCKS];
__device__ unsigned int g_part_ct[NBLOCKS];

// Streaming (evict-first) float4 load: data is single-use per launch.
static __device__ __forceinline__ float4 ldcs4(const float4* p) {
    return __ldcs(p);
}

__global__ void __launch_bounds__(NTHREADS)
wmse_reduce_kernel(const float4* __restrict__ x,
                   const float4* __restrict__ ae,
                   const float4* __restrict__ seg)
{
    float ts = 0.f;        // total sum of diff^2 (all positions, over channels)
    float ps = 0.f;        // sum of diff^2 where seg > 0.5
    unsigned int cnt = 0;  // count of positive spatial positions

    const int stride = NBLOCKS * NTHREADS;
    int v = blockIdx.x * NTHREADS + threadIdx.x;

    #pragma unroll
    for (int it = 0; it < ITERS; ++it, v += stride) {
        // v indexes float4s in the (n,1,h,w) seg tensor. HW4 = 2^16, and HW is
        // divisible by 4, so a float4 never straddles an image boundary.
        const int n_i  = v >> 16;                    // image index  (v / HW4)
        const int s    = v & (HW4 - 1);              // float4 offset within plane
        const int base = n_i * (CC * HW4) + s;       // channel 0 of this image

        const float4 sg = ldcs4(seg + v);
        const float4 x0 = ldcs4(x + base);
        const float4 x1 = ldcs4(x + base + HW4);
        const float4 x2 = ldcs4(x + base + 2 * HW4);
        const float4 a0 = ldcs4(ae + base);
        const float4 a1 = ldcs4(ae + base + HW4);
        const float4 a2 = ldcs4(ae + base + 2 * HW4);

        // Select-form (branchless): guarantees straight-line predicated SASS,
        // no BSSY/BSYNC reconvergence overhead in the hot loop.
        {
            float d0 = a0.x - x0.x, d1 = a1.x - x1.x, d2 = a2.x - x2.x;
            float d  = d0 * d0 + d1 * d1 + d2 * d2;
            ts += d;
            const bool p = sg.x > 0.5f;
            ps  += p ? d : 0.f;
            cnt += p ? 1u : 0u;
        }
        {
            float d0 = a0.y - x0.y, d1 = a1.y - x1.y, d2 = a2.y - x2.y;
            float d  = d0 * d0 + d1 * d1 + d2 * d2;
            ts += d;
            const bool p = sg.y > 0.5f;
            ps  += p ? d : 0.f;
            cnt += p ? 1u : 0u;
        }
        {
            float d0 = a0.z - x0.z, d1 = a1.z - x1.z, d2 = a2.z - x2.z;
            float d  = d0 * d0 + d1 * d1 + d2 * d2;
            ts += d;
            const bool p = sg.z > 0.5f;
            ps  += p ? d : 0.f;
            cnt += p ? 1u : 0u;
        }
        {
            float d0 = a0.w - x0.w, d1 = a1.w - x1.w, d2 = a2.w - x2.w;
            float d  = d0 * d0 + d1 * d1 + d2 * d2;
            ts += d;
            const bool p = sg.w > 0.5f;
            ps  += p ? d : 0.f;
            cnt += p ? 1u : 0u;
        }
    }

    // ---- warp reduction (fixed tree order) ----
    #pragma unroll
    for (int off = 16; off > 0; off >>= 1) {
        ts  += __shfl_down_sync(0xffffffffu, ts,  off);
        ps  += __shfl_down_sync(0xffffffffu, ps,  off);
        cnt += __shfl_down_sync(0xffffffffu, cnt, off);
    }

    // ---- block reduction via shared memory (fixed order) ----
    __shared__ float        s_ts[NTHREADS / 32];
    __shared__ float        s_ps[NTHREADS / 32];
    __shared__ unsigned int s_ct[NTHREADS / 32];

    const int lane = threadIdx.x & 31;
    const int wid  = threadIdx.x >> 5;
    if (lane == 0) { s_ts[wid] = ts; s_ps[wid] = ps; s_ct[wid] = cnt; }
    __syncthreads();

    if (wid == 0 && lane == 0) {
        float tsum = 0.f, psum = 0.f;
        unsigned int c = 0;
        #pragma unroll
        for (int i = 0; i < NTHREADS / 32; ++i) {
            tsum += s_ts[i]; psum += s_ps[i]; c += s_ct[i];
        }
        g_part_ts[blockIdx.x] = tsum;
        g_part_ps[blockIdx.x] = psum;
        g_part_ct[blockIdx.x] = c;
    }
}

// Single-block deterministic final reduction over the 1024 per-block partials.
__global__ void __launch_bounds__(NTHREADS)
wmse_final_kernel(float* __restrict__ out)
{
    const int tid = threadIdx.x;

    // Each thread sums NBLOCKS/NTHREADS = 4 slots in a fixed sequential order.
    double ts = 0.0, ps = 0.0;
    unsigned long long cnt = 0;
    #pragma unroll
    for (int i = 0; i < NBLOCKS / NTHREADS; ++i) {
        const int idx = tid + i * NTHREADS;
        ts  += (double)g_part_ts[idx];
        ps  += (double)g_part_ps[idx];
        cnt += (unsigned long long)g_part_ct[idx];
    }

    // Fixed-topology shared-memory tree reduction (deterministic).
    __shared__ double s_ts[NTHREADS];
    __shared__ double s_ps[NTHREADS];
    __shared__ unsigned long long s_ct[NTHREADS];
    s_ts[tid] = ts; s_ps[tid] = ps; s_ct[tid] = cnt;
    __syncthreads();

    #pragma unroll
    for (int off = NTHREADS / 2; off > 0; off >>= 1) {
        if (tid < off) {
            s_ts[tid] += s_ts[tid + off];
            s_ps[tid] += s_ps[tid + off];
            s_ct[tid] += s_ct[tid + off];
        }
        __syncthreads();
    }

    if (tid == 0) {
        const double pos_num   = (double)s_ct[0];
        const double total     = (double)NHW;
        const double neg_num   = total - pos_num;
        const double pos_ratio = pos_num / total;
        const double neg_ratio = 1.0 - pos_ratio;
        const double cf        = (double)CC;
        const double pos_sum   = s_ps[0];
        const double neg_sum   = s_ts[0] - s_ps[0];
        const double mse_pos   = pos_sum / (pos_num * cf);
        const double mse_neg   = neg_sum / (neg_num * cf);
        out[0] = (float)(pos_ratio * mse_neg + neg_ratio * mse_pos);
    }
}

extern "C" void kernel_launch(void* const* d_in, const int* in_sizes, int n_in,
                              void* d_out, int out_size)
{
    const float4* x   = (const float4*)d_in[0];   // x       (16,3,512,512) f32
    const float4* ae  = (const float4*)d_in[1];   // out_ae  (16,3,512,512) f32
    const float4* seg = (const float4*)d_in[2];   // out_seg (16,1,512,512) f32
    float* out = (float*)d_out;

    wmse_reduce_kernel<<<NBLOCKS, NTHREADS>>>(x, ae, seg);
    wmse_final_kernel<<<1, NTHREADS>>>(out);
}